// round 1
// baseline (speedup 1.0000x reference)
#include <cuda_runtime.h>
#include <math.h>

#define BB 8
#define CC 128
#define PP 2048
#define HH 4
#define CH 512   // CC*HH

// Scratch (device globals — no allocation allowed)
__device__ float g_q[BB*CH*PP];
__device__ float g_k[BB*CH*PP];
__device__ float g_v[BB*CH*PP];
__device__ float g_att[BB*CH*PP];
__device__ float g_s[CC];
__device__ float g_tb[CC];

// ---------------------------------------------------------------------------
// Kernel 1: BatchNorm statistics -> per-channel affine (s, t): xn = x*s + t
// ---------------------------------------------------------------------------
__global__ void bn_stats_kernel(const float* __restrict__ in,
                                const float* __restrict__ gamma,
                                const float* __restrict__ beta) {
    int c = blockIdx.x;
    int tid = threadIdx.x;
    float sum = 0.f, sq = 0.f;
    for (int b = 0; b < BB; b++) {
        const float4* row = (const float4*)(in + (size_t)(b*CC + c)*PP);
        for (int i = tid; i < PP/4; i += 256) {
            float4 v = row[i];
            sum += v.x + v.y + v.z + v.w;
            sq  += v.x*v.x + v.y*v.y + v.z*v.z + v.w*v.w;
        }
    }
    __shared__ float ssum[256], ssq[256];
    ssum[tid] = sum; ssq[tid] = sq;
    __syncthreads();
    for (int o = 128; o > 0; o >>= 1) {
        if (tid < o) { ssum[tid] += ssum[tid+o]; ssq[tid] += ssq[tid+o]; }
        __syncthreads();
    }
    if (tid == 0) {
        const float invN = 1.0f / (BB*PP);
        float mean = ssum[0] * invN;
        float var  = ssq[0] * invN - mean*mean;
        float inv  = rsqrtf(var + 1e-5f);
        float s = gamma[c] * inv;
        g_s[c]  = s;
        g_tb[c] = beta[c] - mean * s;
    }
}

// ---------------------------------------------------------------------------
// Kernel 2: fused normalize + 1x1 conv projection.
// out[b][o][p] = sum_c W[o][c]*(in[b][c][p]*s[c]+t[c]) + bias[o]
// M=512, N=2048 (per batch), K=128.  Block tile 64x64, 256 thr, 4x4 microtile.
// ---------------------------------------------------------------------------
__global__ void gemm_qkv_kernel(const float* __restrict__ W,
                                const float* __restrict__ bias,
                                const float* __restrict__ in,
                                float* __restrict__ out) {
    extern __shared__ float sm[];
    float* Wst = sm;              // [128][64]  (k-major, transposed W tile)
    float* Xs  = sm + 128*64;     // [128][64]
    int b  = blockIdx.z;
    int m0 = blockIdx.y * 64;
    int p0 = blockIdx.x * 64;
    int t  = threadIdx.x;

    // Load W tile transposed (lanes vary rows -> conflict-free smem stores)
    {
        int row = t & 63;
        int c0  = t >> 6;   // 0..3
        const float4* Wp = (const float4*)W;
        #pragma unroll
        for (int it = 0; it < 8; it++) {
            int col4 = c0 + it*4;   // 0..31
            float4 w = Wp[(size_t)(m0+row)*32 + col4];
            Wst[(col4*4+0)*64 + row] = w.x;
            Wst[(col4*4+1)*64 + row] = w.y;
            Wst[(col4*4+2)*64 + row] = w.z;
            Wst[(col4*4+3)*64 + row] = w.w;
        }
    }
    // Load X tile with fused BN affine
    {
        #pragma unroll
        for (int it = 0; it < 8; it++) {
            int idx = t + it*256;
            int c  = idx >> 4;   // 0..127
            int p4 = idx & 15;
            float4 x = *(const float4*)(in + (size_t)(b*CC + c)*PP + p0 + p4*4);
            float s = g_s[c], tb = g_tb[c];
            x.x = x.x*s + tb; x.y = x.y*s + tb;
            x.z = x.z*s + tb; x.w = x.w*s + tb;
            *(float4*)(Xs + c*64 + p4*4) = x;
        }
    }
    __syncthreads();

    int tx = t & 15, ty = t >> 4;
    float acc[4][4];
    #pragma unroll
    for (int r = 0; r < 4; r++)
        #pragma unroll
        for (int cidx = 0; cidx < 4; cidx++) acc[r][cidx] = 0.f;

    #pragma unroll 4
    for (int k = 0; k < 128; k++) {
        float4 a = *(float4*)(Wst + k*64 + ty*4);
        float4 x = *(float4*)(Xs  + k*64 + tx*4);
        acc[0][0] += a.x*x.x; acc[0][1] += a.x*x.y; acc[0][2] += a.x*x.z; acc[0][3] += a.x*x.w;
        acc[1][0] += a.y*x.x; acc[1][1] += a.y*x.y; acc[1][2] += a.y*x.z; acc[1][3] += a.y*x.w;
        acc[2][0] += a.z*x.x; acc[2][1] += a.z*x.y; acc[2][2] += a.z*x.z; acc[2][3] += a.z*x.w;
        acc[3][0] += a.w*x.x; acc[3][1] += a.w*x.y; acc[3][2] += a.w*x.z; acc[3][3] += a.w*x.w;
    }

    #pragma unroll
    for (int r = 0; r < 4; r++) {
        int o = m0 + ty*4 + r;
        float bb = bias[o];
        float4 v;
        v.x = acc[r][0] + bb; v.y = acc[r][1] + bb;
        v.z = acc[r][2] + bb; v.w = acc[r][3] + bb;
        *(float4*)(out + (size_t)(b*CH + o)*PP + p0 + tx*4) = v;
    }
}

// ---------------------------------------------------------------------------
// Kernel 3: flash attention (fp32), per (b,h): D=128, seq=2048.
// Block = 64 queries (8/warp), KV tiles of 64. Warp-synchronous tile body.
// ---------------------------------------------------------------------------
#define FLASH_SMEM ((128*64 + 128*64 + 64*129 + 8*8*64) * 4)

__device__ __forceinline__ float warp_max(float v) {
    #pragma unroll
    for (int off = 16; off > 0; off >>= 1)
        v = fmaxf(v, __shfl_xor_sync(0xffffffffu, v, off));
    return v;
}
__device__ __forceinline__ float warp_sum(float v) {
    #pragma unroll
    for (int off = 16; off > 0; off >>= 1)
        v += __shfl_xor_sync(0xffffffffu, v, off);
    return v;
}

__global__ void flash_kernel(float scale) {
    extern __shared__ float sm[];
    float* Qs  = sm;                 // [128][64]  (c-major, i contiguous), prescaled
    float* Ks  = Qs + 128*64;        // [128][64]
    float* Vst = Ks + 128*64;        // [64][129]  (j-major, d contiguous, padded)
    float* Ps  = Vst + 64*129;       // [8 warps][8][64]
    int b = blockIdx.z, h = blockIdx.y;
    int i0 = blockIdx.x * 64;
    int t = threadIdx.x;
    int w = t >> 5, lane = t & 31;

    const float* qb = g_q + (size_t)b*CH*PP + (size_t)h*PP;
    const float* kb = g_k + (size_t)b*CH*PP + (size_t)h*PP;
    const float* vb = g_v + (size_t)b*CH*PP + (size_t)h*PP;

    // Load Q tile (scaled by c^-0.5)
    #pragma unroll
    for (int it = 0; it < 8; it++) {
        int idx = t + it*256;
        int c = idx >> 4, i4 = idx & 15;
        float4 q = *(const float4*)(qb + (size_t)c*(HH*PP) + i0 + i4*4);
        q.x *= scale; q.y *= scale; q.z *= scale; q.w *= scale;
        *(float4*)(Qs + c*64 + i4*4) = q;
    }

    float m[8], l[8], O[8][4];
    #pragma unroll
    for (int r = 0; r < 8; r++) {
        m[r] = -3.0e38f; l[r] = 0.f;
        O[r][0] = O[r][1] = O[r][2] = O[r][3] = 0.f;
    }

    for (int tile = 0; tile < PP/64; tile++) {
        int j0 = tile * 64;
        __syncthreads();
        // Load K tile [c][j]
        #pragma unroll
        for (int it = 0; it < 8; it++) {
            int idx = t + it*256;
            int c = idx >> 4, j4 = idx & 15;
            float4 kk = *(const float4*)(kb + (size_t)c*(HH*PP) + j0 + j4*4);
            *(float4*)(Ks + c*64 + j4*4) = kk;
        }
        // Load V tile transposed [j][d], row stride 129
        #pragma unroll
        for (int it = 0; it < 8; it++) {
            int idx = t + it*256;
            int c = idx >> 4, j4 = idx & 15;
            float4 vv = *(const float4*)(vb + (size_t)c*(HH*PP) + j0 + j4*4);
            Vst[(j4*4+0)*129 + c] = vv.x;
            Vst[(j4*4+1)*129 + c] = vv.y;
            Vst[(j4*4+2)*129 + c] = vv.z;
            Vst[(j4*4+3)*129 + c] = vv.w;
        }
        __syncthreads();

        // S = (scale*Q)^T K : warp w owns rows i = w*8..w*8+7; lane owns j = 2*lane, 2*lane+1
        float S0[8], S1[8];
        #pragma unroll
        for (int r = 0; r < 8; r++) { S0[r] = 0.f; S1[r] = 0.f; }
        #pragma unroll 2
        for (int c = 0; c < 128; c++) {
            float2 kk = *(float2*)(Ks + c*64 + 2*lane);
            #pragma unroll
            for (int r = 0; r < 8; r++) {
                float qv = Qs[c*64 + w*8 + r];   // warp-broadcast
                S0[r] += qv * kk.x;
                S1[r] += qv * kk.y;
            }
        }

        // Online softmax per row; stage P to per-warp smem
        #pragma unroll
        for (int r = 0; r < 8; r++) {
            float mx = warp_max(fmaxf(S0[r], S1[r]));
            float mn = fmaxf(m[r], mx);
            float al = __expf(m[r] - mn);
            m[r] = mn;
            float p0 = __expf(S0[r] - mn);
            float p1 = __expf(S1[r] - mn);
            float sr = warp_sum(p0 + p1);
            l[r] = l[r]*al + sr;
            O[r][0] *= al; O[r][1] *= al; O[r][2] *= al; O[r][3] *= al;
            *(float2*)(Ps + (w*8+r)*64 + 2*lane) = make_float2(p0, p1);
        }
        __syncwarp();

        // O += P * V^T : lane owns d = lane + 32u
        #pragma unroll 1
        for (int j = 0; j < 64; j++) {
            float v0 = Vst[j*129 + lane];
            float v1 = Vst[j*129 + lane + 32];
            float v2 = Vst[j*129 + lane + 64];
            float v3 = Vst[j*129 + lane + 96];
            #pragma unroll
            for (int r = 0; r < 8; r++) {
                float pr = Ps[(w*8+r)*64 + j];   // warp-broadcast
                O[r][0] += pr*v0; O[r][1] += pr*v1;
                O[r][2] += pr*v2; O[r][3] += pr*v3;
            }
        }
        __syncwarp();
    }

    // Normalize + write att[b][(d*4+h)][i]
    #pragma unroll
    for (int r = 0; r < 8; r++) {
        float inv = 1.f / l[r];
        int i = i0 + w*8 + r;
        #pragma unroll
        for (int u = 0; u < 4; u++) {
            int d = lane + 32*u;
            g_att[(size_t)b*CH*PP + (size_t)(d*HH + h)*PP + i] = O[r][u] * inv;
        }
    }
}

// ---------------------------------------------------------------------------
// Kernel 4: output projection + bias + residual.
// out[b][o][p] = sum_ch Wo[o][ch]*att[b][ch][p] + bo[o] + input[b][o][p]
// M=128, N=2048, K=512 (8 chunks of 64).
// ---------------------------------------------------------------------------
__global__ void gemm_out_kernel(const float* __restrict__ Wo,
                                const float* __restrict__ bo,
                                const float* __restrict__ att,
                                const float* __restrict__ resid,
                                float* __restrict__ out) {
    __shared__ float Wst[64*64];
    __shared__ float As[64*64];
    int b  = blockIdx.z;
    int m0 = blockIdx.y * 64;
    int p0 = blockIdx.x * 64;
    int t  = threadIdx.x;
    int tx = t & 15, ty = t >> 4;

    float acc[4][4];
    #pragma unroll
    for (int r = 0; r < 4; r++)
        #pragma unroll
        for (int cidx = 0; cidx < 4; cidx++) acc[r][cidx] = 0.f;

    for (int kc = 0; kc < 8; kc++) {
        __syncthreads();
        // W chunk, transposed to k-major
        {
            int row = t & 63;
            int c0  = t >> 6;
            const float4* Wp = (const float4*)Wo;
            #pragma unroll
            for (int it = 0; it < 4; it++) {
                int col4 = c0 + it*4;   // 0..15
                float4 w = Wp[(size_t)(m0+row)*128 + kc*16 + col4];
                Wst[(col4*4+0)*64 + row] = w.x;
                Wst[(col4*4+1)*64 + row] = w.y;
                Wst[(col4*4+2)*64 + row] = w.z;
                Wst[(col4*4+3)*64 + row] = w.w;
            }
        }
        // A chunk
        {
            #pragma unroll
            for (int it = 0; it < 4; it++) {
                int idx = t + it*256;
                int c = idx >> 4, p4 = idx & 15;
                float4 x = *(const float4*)(att + (size_t)(b*CH + kc*64 + c)*PP + p0 + p4*4);
                *(float4*)(As + c*64 + p4*4) = x;
            }
        }
        __syncthreads();
        #pragma unroll 4
        for (int k = 0; k < 64; k++) {
            float4 a = *(float4*)(Wst + k*64 + ty*4);
            float4 x = *(float4*)(As  + k*64 + tx*4);
            acc[0][0] += a.x*x.x; acc[0][1] += a.x*x.y; acc[0][2] += a.x*x.z; acc[0][3] += a.x*x.w;
            acc[1][0] += a.y*x.x; acc[1][1] += a.y*x.y; acc[1][2] += a.y*x.z; acc[1][3] += a.y*x.w;
            acc[2][0] += a.z*x.x; acc[2][1] += a.z*x.y; acc[2][2] += a.z*x.z; acc[2][3] += a.z*x.w;
            acc[3][0] += a.w*x.x; acc[3][1] += a.w*x.y; acc[3][2] += a.w*x.z; acc[3][3] += a.w*x.w;
        }
    }

    #pragma unroll
    for (int r = 0; r < 4; r++) {
        int o = m0 + ty*4 + r;
        float bb = bo[o];
        float4 rv = *(const float4*)(resid + (size_t)(b*CC + o)*PP + p0 + tx*4);
        float4 v;
        v.x = acc[r][0] + bb + rv.x; v.y = acc[r][1] + bb + rv.y;
        v.z = acc[r][2] + bb + rv.z; v.w = acc[r][3] + bb + rv.w;
        *(float4*)(out + (size_t)(b*CC + o)*PP + p0 + tx*4) = v;
    }
}

// ---------------------------------------------------------------------------
extern "C" void kernel_launch(void* const* d_in, const int* in_sizes, int n_in,
                              void* d_out, int out_size) {
    (void)in_sizes; (void)n_in; (void)out_size;
    const float* input = (const float*)d_in[0];
    const float* gamma = (const float*)d_in[1];
    const float* beta  = (const float*)d_in[2];
    const float* Wq = (const float*)d_in[3];
    const float* bq = (const float*)d_in[4];
    const float* Wk = (const float*)d_in[5];
    const float* bk = (const float*)d_in[6];
    const float* Wv = (const float*)d_in[7];
    const float* bv = (const float*)d_in[8];
    const float* Wo = (const float*)d_in[9];
    const float* bo = (const float*)d_in[10];
    float* out = (float*)d_out;

    cudaFuncSetAttribute(gemm_qkv_kernel, cudaFuncAttributeMaxDynamicSharedMemorySize, 65536);
    cudaFuncSetAttribute(flash_kernel, cudaFuncAttributeMaxDynamicSharedMemorySize, FLASH_SMEM);

    void *pq, *pk, *pv, *patt;
    cudaGetSymbolAddress(&pq, g_q);
    cudaGetSymbolAddress(&pk, g_k);
    cudaGetSymbolAddress(&pv, g_v);
    cudaGetSymbolAddress(&patt, g_att);

    bn_stats_kernel<<<128, 256>>>(input, gamma, beta);

    dim3 gq(32, 8, 8);
    gemm_qkv_kernel<<<gq, 256, 65536>>>(Wq, bq, input, (float*)pq);
    gemm_qkv_kernel<<<gq, 256, 65536>>>(Wk, bk, input, (float*)pk);
    gemm_qkv_kernel<<<gq, 256, 65536>>>(Wv, bv, input, (float*)pv);

    const float scale = 0.08838834764831845f;  // 128^-0.5
    flash_kernel<<<dim3(32, 4, 8), 256, FLASH_SMEM>>>(scale);

    gemm_out_kernel<<<dim3(32, 2, 8), 256>>>(Wo, bo, (const float*)patt, input, out);
}

// round 3
// speedup vs baseline: 3.7532x; 3.7532x over previous
#include <cuda_runtime.h>
#include <cuda_bf16.h>
#include <stdint.h>
#include <cstdint>
#include <math.h>

#define BB 8
#define CC 128
#define PP 2048
#define HH 4
#define CH 512   // CC*HH

// Scratch (device globals — no allocation allowed)
__device__ __nv_bfloat16 g_q[BB*CH*PP];
__device__ __nv_bfloat16 g_k[BB*CH*PP];
__device__ __nv_bfloat16 g_v[BB*CH*PP];
__device__ float g_att[BB*CH*PP];
__device__ float g_s[CC];
__device__ float g_tb[CC];

__device__ __forceinline__ uint32_t smem_u32(const void* p) {
    return (uint32_t)__cvta_generic_to_shared(p);
}
__device__ __forceinline__ uint32_t pack_bf16(float a, float b) {
    __nv_bfloat162 h = __floats2bfloat162_rn(a, b);
    return *reinterpret_cast<uint32_t*>(&h);
}

#define LDSM_X4_T(r0,r1,r2,r3,addr) \
    asm volatile("ldmatrix.sync.aligned.m8n8.x4.trans.shared.b16 {%0,%1,%2,%3},[%4];" \
        : "=r"(r0),"=r"(r1),"=r"(r2),"=r"(r3) : "r"(addr))
#define LDSM_X2_T(r0,r1,addr) \
    asm volatile("ldmatrix.sync.aligned.m8n8.x2.trans.shared.b16 {%0,%1},[%2];" \
        : "=r"(r0),"=r"(r1) : "r"(addr))
#define LDSM_X2(r0,r1,addr) \
    asm volatile("ldmatrix.sync.aligned.m8n8.x2.shared.b16 {%0,%1},[%2];" \
        : "=r"(r0),"=r"(r1) : "r"(addr))
#define MMA16816(d,a0,a1,a2,a3,b0,b1) \
    asm volatile("mma.sync.aligned.m16n8k16.row.col.f32.bf16.bf16.f32 " \
        "{%0,%1,%2,%3},{%4,%5,%6,%7},{%8,%9},{%0,%1,%2,%3};" \
        : "+f"(d[0]),"+f"(d[1]),"+f"(d[2]),"+f"(d[3]) \
        : "r"(a0),"r"(a1),"r"(a2),"r"(a3),"r"(b0),"r"(b1))

// ---------------------------------------------------------------------------
// Kernel 1: BatchNorm statistics -> per-channel affine (s, t): xn = x*s + t
// ---------------------------------------------------------------------------
__global__ void bn_stats_kernel(const float* __restrict__ in,
                                const float* __restrict__ gamma,
                                const float* __restrict__ beta) {
    int c = blockIdx.x;
    int tid = threadIdx.x;
    float sum = 0.f, sq = 0.f;
    for (int b = 0; b < BB; b++) {
        const float4* row = (const float4*)(in + (size_t)(b*CC + c)*PP);
        for (int i = tid; i < PP/4; i += 256) {
            float4 v = row[i];
            sum += v.x + v.y + v.z + v.w;
            sq  += v.x*v.x + v.y*v.y + v.z*v.z + v.w*v.w;
        }
    }
    __shared__ float ssum[256], ssq[256];
    ssum[tid] = sum; ssq[tid] = sq;
    __syncthreads();
    for (int o = 128; o > 0; o >>= 1) {
        if (tid < o) { ssum[tid] += ssum[tid+o]; ssq[tid] += ssq[tid+o]; }
        __syncthreads();
    }
    if (tid == 0) {
        const float invN = 1.0f / (BB*PP);
        float mean = ssum[0] * invN;
        float var  = ssq[0] * invN - mean*mean;
        float inv  = rsqrtf(var + 1e-5f);
        float s = gamma[c] * inv;
        g_s[c]  = s;
        g_tb[c] = beta[c] - mean * s;
    }
}

// ---------------------------------------------------------------------------
// Kernel 2: fused normalize + 1x1 conv projection, bf16 output (Q pre-scaled).
// out[b][o][p] = (sum_c W[o][c]*(in[b][c][p]*s[c]+t[c]) + bias[o]) * scale
// ---------------------------------------------------------------------------
__global__ void gemm_qkv_kernel(const float* __restrict__ W,
                                const float* __restrict__ bias,
                                const float* __restrict__ in,
                                __nv_bfloat16* __restrict__ out,
                                float scale) {
    extern __shared__ float sm[];
    float* Wst = sm;              // [128][64]  (k-major)
    float* Xs  = sm + 128*64;     // [128][64]
    int b  = blockIdx.z;
    int m0 = blockIdx.y * 64;
    int p0 = blockIdx.x * 64;
    int t  = threadIdx.x;

    {
        int row = t & 63;
        int c0  = t >> 6;
        const float4* Wp = (const float4*)W;
        #pragma unroll
        for (int it = 0; it < 8; it++) {
            int col4 = c0 + it*4;
            float4 w = Wp[(size_t)(m0+row)*32 + col4];
            Wst[(col4*4+0)*64 + row] = w.x;
            Wst[(col4*4+1)*64 + row] = w.y;
            Wst[(col4*4+2)*64 + row] = w.z;
            Wst[(col4*4+3)*64 + row] = w.w;
        }
    }
    {
        #pragma unroll
        for (int it = 0; it < 8; it++) {
            int idx = t + it*256;
            int c  = idx >> 4;
            int p4 = idx & 15;
            float4 x = *(const float4*)(in + (size_t)(b*CC + c)*PP + p0 + p4*4);
            float s = g_s[c], tb = g_tb[c];
            x.x = x.x*s + tb; x.y = x.y*s + tb;
            x.z = x.z*s + tb; x.w = x.w*s + tb;
            *(float4*)(Xs + c*64 + p4*4) = x;
        }
    }
    __syncthreads();

    int tx = t & 15, ty = t >> 4;
    float acc[4][4];
    #pragma unroll
    for (int r = 0; r < 4; r++)
        #pragma unroll
        for (int cidx = 0; cidx < 4; cidx++) acc[r][cidx] = 0.f;

    #pragma unroll 4
    for (int k = 0; k < 128; k++) {
        float4 a = *(float4*)(Wst + k*64 + ty*4);
        float4 x = *(float4*)(Xs  + k*64 + tx*4);
        acc[0][0] += a.x*x.x; acc[0][1] += a.x*x.y; acc[0][2] += a.x*x.z; acc[0][3] += a.x*x.w;
        acc[1][0] += a.y*x.x; acc[1][1] += a.y*x.y; acc[1][2] += a.y*x.z; acc[1][3] += a.y*x.w;
        acc[2][0] += a.z*x.x; acc[2][1] += a.z*x.y; acc[2][2] += a.z*x.z; acc[2][3] += a.z*x.w;
        acc[3][0] += a.w*x.x; acc[3][1] += a.w*x.y; acc[3][2] += a.w*x.z; acc[3][3] += a.w*x.w;
    }

    #pragma unroll
    for (int r = 0; r < 4; r++) {
        int o = m0 + ty*4 + r;
        float bb = bias[o];
        float v0 = (acc[r][0] + bb) * scale;
        float v1 = (acc[r][1] + bb) * scale;
        float v2 = (acc[r][2] + bb) * scale;
        float v3 = (acc[r][3] + bb) * scale;
        uint2 pk;
        pk.x = pack_bf16(v0, v1);
        pk.y = pack_bf16(v2, v3);
        *(uint2*)(out + (size_t)(b*CH + o)*PP + p0 + tx*4) = pk;
    }
}

// ---------------------------------------------------------------------------
// Kernel 3: flash attention, bf16 mma.sync tensor cores, fp32 softmax/accum.
// Br=128 (8 warps x 16 rows), Bc=64, D=128. All smem tiles in natural [c][p]
// layout; trans/non-trans ldmatrix picks the right fragments (no transposes).
// ---------------------------------------------------------------------------
#define QSTR 136   // 128 + 8 pad (bf16 elems); row stride 272B -> conflict-free
#define KSTR 72    // 64 + 8 pad; row stride 144B
#define FLASH_SMEM ((128*QSTR + 128*KSTR + 128*KSTR) * 2)

__global__ __launch_bounds__(256, 1) void flash_kernel() {
    extern __shared__ char smraw[];
    __nv_bfloat16* Qs = (__nv_bfloat16*)smraw;        // [c=128][i=128]
    __nv_bfloat16* Ks = Qs + 128*QSTR;                // [c=128][j=64]
    __nv_bfloat16* Vs = Ks + 128*KSTR;                // [d=128][j=64]

    int b = blockIdx.z, h = blockIdx.y;
    int i0 = blockIdx.x * 128;
    int t = threadIdx.x;
    int w = t >> 5, lane = t & 31;

    const __nv_bfloat16* qb = g_q + (size_t)b*CH*PP + (size_t)h*PP;
    const __nv_bfloat16* kb = g_k + (size_t)b*CH*PP + (size_t)h*PP;
    const __nv_bfloat16* vb = g_v + (size_t)b*CH*PP + (size_t)h*PP;

    // Load Q tile [c][i] (already scaled by c^-0.5 at projection)
    #pragma unroll
    for (int it = 0; it < 8; it++) {
        int idx = t + it*256;
        int c = idx >> 4, u = idx & 15;
        uint4 val = *(const uint4*)(qb + (size_t)c*(HH*PP) + i0 + u*8);
        *(uint4*)(Qs + c*QSTR + u*8) = val;
    }

    // Per-thread ldmatrix lane addresses
    uint32_t qs0 = smem_u32(Qs), ks0 = smem_u32(Ks), vs0 = smem_u32(Vs);
    // A (Q, x4.trans): rows c = (lane&7)+8*((lane>>4)&1); cols i = 16w+8*((lane>>3)&1)
    uint32_t aAddr = qs0 + ((lane&7) + 8*((lane>>4)&1)) * (QSTR*2)
                         + (16*w + 8*((lane>>3)&1)) * 2;
    // B (K, x2.trans): rows c = (lane&7)+8*((lane>>3)&1); col j set per nb
    uint32_t kAddr = ks0 + ((lane&7) + 8*((lane>>3)&1)) * (KSTR*2);
    // B (V, x2 non-trans): rows d = (lane&7); col j +8 elems for lanes 8-15
    uint32_t vAddr = vs0 + (lane&7) * (KSTR*2) + ((lane>>3)&1) * 16;

    float m0 = -1e30f, m1 = -1e30f, l0 = 0.f, l1 = 0.f;
    float O[16][4];
    #pragma unroll
    for (int nb = 0; nb < 16; nb++)
        O[nb][0] = O[nb][1] = O[nb][2] = O[nb][3] = 0.f;

    for (int tile = 0; tile < PP/64; tile++) {
        int j0g = tile * 64;
        __syncthreads();
        // Load K,V tiles [c][j], [d][j]
        #pragma unroll
        for (int it = 0; it < 4; it++) {
            int idx = t + it*256;
            int c = idx >> 3, u = idx & 7;
            *(uint4*)(Ks + c*KSTR + u*8) =
                *(const uint4*)(kb + (size_t)c*(HH*PP) + j0g + u*8);
            *(uint4*)(Vs + c*KSTR + u*8) =
                *(const uint4*)(vb + (size_t)c*(HH*PP) + j0g + u*8);
        }
        __syncthreads();

        // S = Q^T K  (warp's 16 rows x 64 cols)
        float sv[8][4];
        #pragma unroll
        for (int nb = 0; nb < 8; nb++)
            sv[nb][0] = sv[nb][1] = sv[nb][2] = sv[nb][3] = 0.f;

        #pragma unroll
        for (int kk = 0; kk < 8; kk++) {
            uint32_t a0, a1, a2, a3;
            LDSM_X4_T(a0, a1, a2, a3, aAddr + kk*16*(QSTR*2));
            #pragma unroll
            for (int nb = 0; nb < 8; nb++) {
                uint32_t b0, b1;
                LDSM_X2_T(b0, b1, kAddr + kk*16*(KSTR*2) + nb*16);
                MMA16816(sv[nb], a0, a1, a2, a3, b0, b1);
            }
        }

        // Online softmax (rows r0=lane/4, r1=r0+8; cols shared by lane%4 group)
        float rmax0 = -1e30f, rmax1 = -1e30f;
        #pragma unroll
        for (int nb = 0; nb < 8; nb++) {
            rmax0 = fmaxf(rmax0, fmaxf(sv[nb][0], sv[nb][1]));
            rmax1 = fmaxf(rmax1, fmaxf(sv[nb][2], sv[nb][3]));
        }
        rmax0 = fmaxf(rmax0, __shfl_xor_sync(0xffffffffu, rmax0, 1));
        rmax0 = fmaxf(rmax0, __shfl_xor_sync(0xffffffffu, rmax0, 2));
        rmax1 = fmaxf(rmax1, __shfl_xor_sync(0xffffffffu, rmax1, 1));
        rmax1 = fmaxf(rmax1, __shfl_xor_sync(0xffffffffu, rmax1, 2));
        float mn0 = fmaxf(m0, rmax0), mn1 = fmaxf(m1, rmax1);
        float al0 = __expf(m0 - mn0), al1 = __expf(m1 - mn1);
        m0 = mn0; m1 = mn1;
        float rs0 = 0.f, rs1 = 0.f;
        #pragma unroll
        for (int nb = 0; nb < 8; nb++) {
            sv[nb][0] = __expf(sv[nb][0] - mn0);
            sv[nb][1] = __expf(sv[nb][1] - mn0);
            sv[nb][2] = __expf(sv[nb][2] - mn1);
            sv[nb][3] = __expf(sv[nb][3] - mn1);
            rs0 += sv[nb][0] + sv[nb][1];
            rs1 += sv[nb][2] + sv[nb][3];
        }
        rs0 += __shfl_xor_sync(0xffffffffu, rs0, 1);
        rs0 += __shfl_xor_sync(0xffffffffu, rs0, 2);
        rs1 += __shfl_xor_sync(0xffffffffu, rs1, 1);
        rs1 += __shfl_xor_sync(0xffffffffu, rs1, 2);
        l0 = l0*al0 + rs0;
        l1 = l1*al1 + rs1;
        #pragma unroll
        for (int nb = 0; nb < 16; nb++) {
            O[nb][0] *= al0; O[nb][1] *= al0;
            O[nb][2] *= al1; O[nb][3] *= al1;
        }

        // P (accum layout) -> A fragments, in registers
        uint32_t pa[4][4];
        #pragma unroll
        for (int kbk = 0; kbk < 4; kbk++) {
            pa[kbk][0] = pack_bf16(sv[2*kbk][0],   sv[2*kbk][1]);
            pa[kbk][1] = pack_bf16(sv[2*kbk][2],   sv[2*kbk][3]);
            pa[kbk][2] = pack_bf16(sv[2*kbk+1][0], sv[2*kbk+1][1]);
            pa[kbk][3] = pack_bf16(sv[2*kbk+1][2], sv[2*kbk+1][3]);
        }

        // O += P V^T
        #pragma unroll
        for (int kbk = 0; kbk < 4; kbk++) {
            #pragma unroll
            for (int nb = 0; nb < 16; nb++) {
                uint32_t b0, b1;
                LDSM_X2(b0, b1, vAddr + nb*8*(KSTR*2) + kbk*32);
                MMA16816(O[nb], pa[kbk][0], pa[kbk][1], pa[kbk][2], pa[kbk][3], b0, b1);
            }
        }
    }

    // Normalize + store att[b][(d*HH+h)][i]  (fp32)
    float inv0 = 1.f / l0, inv1 = 1.f / l1;
    size_t obase = (size_t)b*CH*PP + (size_t)h*PP;
    int irow = i0 + 16*w + (lane >> 2);
    #pragma unroll
    for (int nb = 0; nb < 16; nb++) {
        int d0 = 8*nb + 2*(lane & 3);
        g_att[obase + (size_t)(d0  )*HH*PP + irow    ] = O[nb][0] * inv0;
        g_att[obase + (size_t)(d0+1)*HH*PP + irow    ] = O[nb][1] * inv0;
        g_att[obase + (size_t)(d0  )*HH*PP + irow + 8] = O[nb][2] * inv1;
        g_att[obase + (size_t)(d0+1)*HH*PP + irow + 8] = O[nb][3] * inv1;
    }
}

// ---------------------------------------------------------------------------
// Kernel 4: output projection + bias + residual (fp32).
// ---------------------------------------------------------------------------
__global__ void gemm_out_kernel(const float* __restrict__ Wo,
                                const float* __restrict__ bo,
                                const float* __restrict__ att,
                                const float* __restrict__ resid,
                                float* __restrict__ out) {
    __shared__ float Wst[64*64];
    __shared__ float As[64*64];
    int b  = blockIdx.z;
    int m0 = blockIdx.y * 64;
    int p0 = blockIdx.x * 64;
    int t  = threadIdx.x;
    int tx = t & 15, ty = t >> 4;

    float acc[4][4];
    #pragma unroll
    for (int r = 0; r < 4; r++)
        #pragma unroll
        for (int cidx = 0; cidx < 4; cidx++) acc[r][cidx] = 0.f;

    for (int kc = 0; kc < 8; kc++) {
        __syncthreads();
        {
            int row = t & 63;
            int c0  = t >> 6;
            const float4* Wp = (const float4*)Wo;
            #pragma unroll
            for (int it = 0; it < 4; it++) {
                int col4 = c0 + it*4;
                float4 w = Wp[(size_t)(m0+row)*128 + kc*16 + col4];
                Wst[(col4*4+0)*64 + row] = w.x;
                Wst[(col4*4+1)*64 + row] = w.y;
                Wst[(col4*4+2)*64 + row] = w.z;
                Wst[(col4*4+3)*64 + row] = w.w;
            }
        }
        {
            #pragma unroll
            for (int it = 0; it < 4; it++) {
                int idx = t + it*256;
                int c = idx >> 4, p4 = idx & 15;
                float4 x = *(const float4*)(att + (size_t)(b*CH + kc*64 + c)*PP + p0 + p4*4);
                *(float4*)(As + c*64 + p4*4) = x;
            }
        }
        __syncthreads();
        #pragma unroll 4
        for (int k = 0; k < 64; k++) {
            float4 a = *(float4*)(Wst + k*64 + ty*4);
            float4 x = *(float4*)(As  + k*64 + tx*4);
            acc[0][0] += a.x*x.x; acc[0][1] += a.x*x.y; acc[0][2] += a.x*x.z; acc[0][3] += a.x*x.w;
            acc[1][0] += a.y*x.x; acc[1][1] += a.y*x.y; acc[1][2] += a.y*x.z; acc[1][3] += a.y*x.w;
            acc[2][0] += a.z*x.x; acc[2][1] += a.z*x.y; acc[2][2] += a.z*x.z; acc[2][3] += a.z*x.w;
            acc[3][0] += a.w*x.x; acc[3][1] += a.w*x.y; acc[3][2] += a.w*x.z; acc[3][3] += a.w*x.w;
        }
    }

    #pragma unroll
    for (int r = 0; r < 4; r++) {
        int o = m0 + ty*4 + r;
        float bb = bo[o];
        float4 rv = *(const float4*)(resid + (size_t)(b*CC + o)*PP + p0 + tx*4);
        float4 v;
        v.x = acc[r][0] + bb + rv.x; v.y = acc[r][1] + bb + rv.y;
        v.z = acc[r][2] + bb + rv.z; v.w = acc[r][3] + bb + rv.w;
        *(float4*)(out + (size_t)(b*CC + o)*PP + p0 + tx*4) = v;
    }
}

// ---------------------------------------------------------------------------
extern "C" void kernel_launch(void* const* d_in, const int* in_sizes, int n_in,
                              void* d_out, int out_size) {
    (void)in_sizes; (void)n_in; (void)out_size;
    const float* input = (const float*)d_in[0];
    const float* gamma = (const float*)d_in[1];
    const float* beta  = (const float*)d_in[2];
    const float* Wq = (const float*)d_in[3];
    const float* bq = (const float*)d_in[4];
    const float* Wk = (const float*)d_in[5];
    const float* bk = (const float*)d_in[6];
    const float* Wv = (const float*)d_in[7];
    const float* bv = (const float*)d_in[8];
    const float* Wo = (const float*)d_in[9];
    const float* bo = (const float*)d_in[10];
    float* out = (float*)d_out;

    cudaFuncSetAttribute(gemm_qkv_kernel, cudaFuncAttributeMaxDynamicSharedMemorySize, 65536);
    cudaFuncSetAttribute(flash_kernel, cudaFuncAttributeMaxDynamicSharedMemorySize, FLASH_SMEM);

    void *pq, *pk, *pv, *patt;
    cudaGetSymbolAddress(&pq, g_q);
    cudaGetSymbolAddress(&pk, g_k);
    cudaGetSymbolAddress(&pv, g_v);
    cudaGetSymbolAddress(&patt, g_att);

    bn_stats_kernel<<<128, 256>>>(input, gamma, beta);

    const float scale = 0.08838834764831845f;  // 128^-0.5
    dim3 gq(32, 8, 8);
    gemm_qkv_kernel<<<gq, 256, 65536>>>(Wq, bq, input, (__nv_bfloat16*)pq, scale);
    gemm_qkv_kernel<<<gq, 256, 65536>>>(Wk, bk, input, (__nv_bfloat16*)pk, 1.0f);
    gemm_qkv_kernel<<<gq, 256, 65536>>>(Wv, bv, input, (__nv_bfloat16*)pv, 1.0f);

    flash_kernel<<<dim3(16, 4, 8), 256, FLASH_SMEM>>>();

    gemm_out_kernel<<<dim3(32, 2, 8), 256>>>(Wo, bo, (const float*)patt, input, out);
}

// round 4
// speedup vs baseline: 6.2042x; 1.6531x over previous
#include <cuda_runtime.h>
#include <cuda_bf16.h>
#include <stdint.h>
#include <cstdint>
#include <math.h>

#define BB 8
#define CC 128
#define PP 2048
#define HH 4
#define CH 512   // CC*HH

// Scratch (device globals — no allocation allowed)
__device__ __nv_bfloat16 g_q[BB*CH*PP];
__device__ __nv_bfloat16 g_k[BB*CH*PP];
__device__ __nv_bfloat16 g_v[BB*CH*PP];
__device__ __nv_bfloat16 g_att[BB*CH*PP];
__device__ float g_s[CC];
__device__ float g_tb[CC];

__device__ __forceinline__ uint32_t smem_u32(const void* p) {
    return (uint32_t)__cvta_generic_to_shared(p);
}
__device__ __forceinline__ uint32_t pack_bf16(float a, float b) {
    __nv_bfloat162 h = __floats2bfloat162_rn(a, b);
    return *reinterpret_cast<uint32_t*>(&h);
}

#define LDSM_X4(r0,r1,r2,r3,addr) \
    asm volatile("ldmatrix.sync.aligned.m8n8.x4.shared.b16 {%0,%1,%2,%3},[%4];" \
        : "=r"(r0),"=r"(r1),"=r"(r2),"=r"(r3) : "r"(addr))
#define LDSM_X4_T(r0,r1,r2,r3,addr) \
    asm volatile("ldmatrix.sync.aligned.m8n8.x4.trans.shared.b16 {%0,%1,%2,%3},[%4];" \
        : "=r"(r0),"=r"(r1),"=r"(r2),"=r"(r3) : "r"(addr))
#define MMA16816(d,a0,a1,a2,a3,b0,b1) \
    asm volatile("mma.sync.aligned.m16n8k16.row.col.f32.bf16.bf16.f32 " \
        "{%0,%1,%2,%3},{%4,%5,%6,%7},{%8,%9},{%0,%1,%2,%3};" \
        : "+f"(d[0]),"+f"(d[1]),"+f"(d[2]),"+f"(d[3]) \
        : "r"(a0),"r"(a1),"r"(a2),"r"(a3),"r"(b0),"r"(b1))

// ---------------------------------------------------------------------------
// Kernel 1: BatchNorm statistics -> per-channel affine (s, t): xn = x*s + t
// ---------------------------------------------------------------------------
__global__ void bn_stats_kernel(const float* __restrict__ in,
                                const float* __restrict__ gamma,
                                const float* __restrict__ beta) {
    int c = blockIdx.x;
    int tid = threadIdx.x;
    float sum = 0.f, sq = 0.f;
    for (int b = 0; b < BB; b++) {
        const float4* row = (const float4*)(in + (size_t)(b*CC + c)*PP);
        for (int i = tid; i < PP/4; i += 256) {
            float4 v = row[i];
            sum += v.x + v.y + v.z + v.w;
            sq  += v.x*v.x + v.y*v.y + v.z*v.z + v.w*v.w;
        }
    }
    __shared__ float ssum[256], ssq[256];
    ssum[tid] = sum; ssq[tid] = sq;
    __syncthreads();
    for (int o = 128; o > 0; o >>= 1) {
        if (tid < o) { ssum[tid] += ssum[tid+o]; ssq[tid] += ssq[tid+o]; }
        __syncthreads();
    }
    if (tid == 0) {
        const float invN = 1.0f / (BB*PP);
        float mean = ssum[0] * invN;
        float var  = ssq[0] * invN - mean*mean;
        float inv  = rsqrtf(var + 1e-5f);
        float s = gamma[c] * inv;
        g_s[c]  = s;
        g_tb[c] = beta[c] - mean * s;
    }
}

// ---------------------------------------------------------------------------
// Kernel 2: fused QKV projection on tensor cores (bf16 mma.sync).
// Block: 128 out-rows x 128 points, K=128. Grid y: 12 m-tiles (4 per segment
// Q/K/V). A = W (row-major, non-trans ldmatrix), B = Xnorm (trans ldmatrix).
// ---------------------------------------------------------------------------
#define WSTR 136
#define XSTR 136
#define QKV_SMEM ((128*WSTR + 128*XSTR) * 2)

__global__ __launch_bounds__(256, 2) void qkv_mma_kernel(
        const float* __restrict__ Wq, const float* __restrict__ bq,
        const float* __restrict__ Wk, const float* __restrict__ bk,
        const float* __restrict__ Wv, const float* __restrict__ bv,
        const float* __restrict__ in) {
    extern __shared__ char smraw[];
    __nv_bfloat16* Ws = (__nv_bfloat16*)smraw;   // [m=128][k=128]
    __nv_bfloat16* Xs = Ws + 128*WSTR;           // [k=128][p=128]

    int b  = blockIdx.z;
    int mt = blockIdx.y;           // 0..11
    int p0 = blockIdx.x * 128;
    int seg = mt >> 2;
    int m0  = (mt & 3) * 128;
    const float* W; const float* bias; __nv_bfloat16* out; float scale;
    if (seg == 0)      { W = Wq; bias = bq; out = g_q; scale = 0.08838834764831845f; }
    else if (seg == 1) { W = Wk; bias = bk; out = g_k; scale = 1.0f; }
    else               { W = Wv; bias = bv; out = g_v; scale = 1.0f; }

    int t = threadIdx.x;
    // Load W tile [128][128] fp32 -> bf16
    #pragma unroll
    for (int it = 0; it < 16; it++) {
        int idx = t + it*256;
        int row = idx >> 5, col4 = idx & 31;
        float4 w = *(const float4*)(W + (size_t)(m0+row)*CC + col4*4);
        uint2 pk; pk.x = pack_bf16(w.x, w.y); pk.y = pack_bf16(w.z, w.w);
        *(uint2*)(Ws + row*WSTR + col4*4) = pk;
    }
    // Load X tile with BN affine, fp32 -> bf16
    #pragma unroll
    for (int it = 0; it < 16; it++) {
        int idx = t + it*256;
        int c = idx >> 5, p4 = idx & 31;
        float4 x = *(const float4*)(in + (size_t)(b*CC + c)*PP + p0 + p4*4);
        float s = g_s[c], tb = g_tb[c];
        uint2 pk;
        pk.x = pack_bf16(x.x*s + tb, x.y*s + tb);
        pk.y = pack_bf16(x.z*s + tb, x.w*s + tb);
        *(uint2*)(Xs + c*XSTR + p4*4) = pk;
    }
    __syncthreads();

    int w = t >> 5, lane = t & 31;
    int wm = w & 3, wn = w >> 2;   // warp tile: rows wm*32..+31, cols wn*64..+63

    uint32_t aAddr = smem_u32(Ws)
        + (wm*32 + (lane&7) + 8*((lane>>3)&1)) * (WSTR*2)
        + ((lane>>4)&1) * 16;
    uint32_t bAddr = smem_u32(Xs)
        + ((lane&7) + 8*((lane>>3)&1)) * (XSTR*2)
        + ((lane>>4)&1) * 16
        + wn*128;

    float acc[2][8][4];
    #pragma unroll
    for (int i = 0; i < 2; i++)
        #pragma unroll
        for (int j = 0; j < 8; j++)
            acc[i][j][0] = acc[i][j][1] = acc[i][j][2] = acc[i][j][3] = 0.f;

    #pragma unroll
    for (int kk = 0; kk < 8; kk++) {
        uint32_t a[2][4];
        LDSM_X4(a[0][0], a[0][1], a[0][2], a[0][3], aAddr + kk*32);
        LDSM_X4(a[1][0], a[1][1], a[1][2], a[1][3], aAddr + 16*(WSTR*2) + kk*32);
        #pragma unroll
        for (int nb2 = 0; nb2 < 4; nb2++) {
            uint32_t b0, b1, b2, b3;
            LDSM_X4_T(b0, b1, b2, b3, bAddr + kk*16*(XSTR*2) + nb2*32);
            #pragma unroll
            for (int mt2 = 0; mt2 < 2; mt2++) {
                MMA16816(acc[mt2][2*nb2  ], a[mt2][0], a[mt2][1], a[mt2][2], a[mt2][3], b0, b1);
                MMA16816(acc[mt2][2*nb2+1], a[mt2][0], a[mt2][1], a[mt2][2], a[mt2][3], b2, b3);
            }
        }
    }

    // Epilogue: + bias, * scale, bf16 store
    #pragma unroll
    for (int mt2 = 0; mt2 < 2; mt2++) {
        int r0 = m0 + wm*32 + mt2*16 + (lane >> 2);
        float bb0 = (bias[r0] ) * 1.0f;
        float bb1 = (bias[r0+8]) * 1.0f;
        #pragma unroll
        for (int nb = 0; nb < 8; nb++) {
            int n = p0 + wn*64 + nb*8 + (lane&3)*2;
            *(uint32_t*)(out + (size_t)(b*CH + r0  )*PP + n) =
                pack_bf16((acc[mt2][nb][0] + bb0)*scale, (acc[mt2][nb][1] + bb0)*scale);
            *(uint32_t*)(out + (size_t)(b*CH + r0+8)*PP + n) =
                pack_bf16((acc[mt2][nb][2] + bb1)*scale, (acc[mt2][nb][3] + bb1)*scale);
        }
    }
}

// ---------------------------------------------------------------------------
// Kernel 3: flash attention, bf16 mma.sync tensor cores, fp32 softmax/accum.
// Br=128 (8 warps x 16 rows), Bc=64, D=128. x4 ldmatrix everywhere.
// ---------------------------------------------------------------------------
#define QSTR 136   // 128 + 8 pad (bf16 elems)
#define KSTR 72    // 64 + 8 pad
#define FLASH_SMEM ((128*QSTR + 128*KSTR + 128*KSTR) * 2)

__global__ __launch_bounds__(256, 1) void flash_kernel() {
    extern __shared__ char smraw[];
    __nv_bfloat16* Qs = (__nv_bfloat16*)smraw;        // [c=128][i=128]
    __nv_bfloat16* Ks = Qs + 128*QSTR;                // [c=128][j=64]
    __nv_bfloat16* Vs = Ks + 128*KSTR;                // [d=128][j=64]

    int b = blockIdx.z, h = blockIdx.y;
    int i0 = blockIdx.x * 128;
    int t = threadIdx.x;
    int w = t >> 5, lane = t & 31;

    const __nv_bfloat16* qb = g_q + (size_t)b*CH*PP + (size_t)h*PP;
    const __nv_bfloat16* kb = g_k + (size_t)b*CH*PP + (size_t)h*PP;
    const __nv_bfloat16* vb = g_v + (size_t)b*CH*PP + (size_t)h*PP;

    #pragma unroll
    for (int it = 0; it < 8; it++) {
        int idx = t + it*256;
        int c = idx >> 4, u = idx & 15;
        *(uint4*)(Qs + c*QSTR + u*8) =
            *(const uint4*)(qb + (size_t)c*(HH*PP) + i0 + u*8);
    }

    uint32_t qs0 = smem_u32(Qs), ks0 = smem_u32(Ks), vs0 = smem_u32(Vs);
    uint32_t aAddr = qs0 + ((lane&7) + 8*((lane>>4)&1)) * (QSTR*2)
                         + (16*w + 8*((lane>>3)&1)) * 2;
    // K x4.trans: groups 0,1 -> rows c0-7/c8-15 at col j; groups 2,3 -> col j+8
    uint32_t kAddr = ks0 + ((lane&7) + 8*((lane>>3)&1)) * (KSTR*2)
                         + ((lane>>4)&1) * 16;
    // V x4 non-trans: groups 0,1 -> d rows nb*8.. cols j/j+8; groups 2,3 -> d rows +8
    uint32_t vAddr = vs0 + (lane&7) * (KSTR*2) + ((lane>>3)&1) * 16
                         + ((lane>>4)&1) * (8*(KSTR*2));

    float m0 = -1e30f, m1 = -1e30f, l0 = 0.f, l1 = 0.f;
    float O[16][4];
    #pragma unroll
    for (int nb = 0; nb < 16; nb++)
        O[nb][0] = O[nb][1] = O[nb][2] = O[nb][3] = 0.f;

    for (int tile = 0; tile < PP/64; tile++) {
        int j0g = tile * 64;
        __syncthreads();
        #pragma unroll
        for (int it = 0; it < 4; it++) {
            int idx = t + it*256;
            int c = idx >> 3, u = idx & 7;
            *(uint4*)(Ks + c*KSTR + u*8) =
                *(const uint4*)(kb + (size_t)c*(HH*PP) + j0g + u*8);
            *(uint4*)(Vs + c*KSTR + u*8) =
                *(const uint4*)(vb + (size_t)c*(HH*PP) + j0g + u*8);
        }
        __syncthreads();

        // S = Q^T K
        float sv[8][4];
        #pragma unroll
        for (int nb = 0; nb < 8; nb++)
            sv[nb][0] = sv[nb][1] = sv[nb][2] = sv[nb][3] = 0.f;

        #pragma unroll
        for (int kk = 0; kk < 8; kk++) {
            uint32_t a0, a1, a2, a3;
            LDSM_X4_T(a0, a1, a2, a3, aAddr + kk*16*(QSTR*2));
            #pragma unroll
            for (int nb2 = 0; nb2 < 4; nb2++) {
                uint32_t b0, b1, b2, b3;
                LDSM_X4_T(b0, b1, b2, b3, kAddr + kk*16*(KSTR*2) + nb2*32);
                MMA16816(sv[2*nb2  ], a0, a1, a2, a3, b0, b1);
                MMA16816(sv[2*nb2+1], a0, a1, a2, a3, b2, b3);
            }
        }

        // Online softmax
        float rmax0 = -1e30f, rmax1 = -1e30f;
        #pragma unroll
        for (int nb = 0; nb < 8; nb++) {
            rmax0 = fmaxf(rmax0, fmaxf(sv[nb][0], sv[nb][1]));
            rmax1 = fmaxf(rmax1, fmaxf(sv[nb][2], sv[nb][3]));
        }
        rmax0 = fmaxf(rmax0, __shfl_xor_sync(0xffffffffu, rmax0, 1));
        rmax0 = fmaxf(rmax0, __shfl_xor_sync(0xffffffffu, rmax0, 2));
        rmax1 = fmaxf(rmax1, __shfl_xor_sync(0xffffffffu, rmax1, 1));
        rmax1 = fmaxf(rmax1, __shfl_xor_sync(0xffffffffu, rmax1, 2));
        float mn0 = fmaxf(m0, rmax0), mn1 = fmaxf(m1, rmax1);
        float al0 = __expf(m0 - mn0), al1 = __expf(m1 - mn1);
        m0 = mn0; m1 = mn1;
        float rs0 = 0.f, rs1 = 0.f;
        #pragma unroll
        for (int nb = 0; nb < 8; nb++) {
            sv[nb][0] = __expf(sv[nb][0] - mn0);
            sv[nb][1] = __expf(sv[nb][1] - mn0);
            sv[nb][2] = __expf(sv[nb][2] - mn1);
            sv[nb][3] = __expf(sv[nb][3] - mn1);
            rs0 += sv[nb][0] + sv[nb][1];
            rs1 += sv[nb][2] + sv[nb][3];
        }
        rs0 += __shfl_xor_sync(0xffffffffu, rs0, 1);
        rs0 += __shfl_xor_sync(0xffffffffu, rs0, 2);
        rs1 += __shfl_xor_sync(0xffffffffu, rs1, 1);
        rs1 += __shfl_xor_sync(0xffffffffu, rs1, 2);
        l0 = l0*al0 + rs0;
        l1 = l1*al1 + rs1;
        #pragma unroll
        for (int nb = 0; nb < 16; nb++) {
            O[nb][0] *= al0; O[nb][1] *= al0;
            O[nb][2] *= al1; O[nb][3] *= al1;
        }

        uint32_t pa[4][4];
        #pragma unroll
        for (int kbk = 0; kbk < 4; kbk++) {
            pa[kbk][0] = pack_bf16(sv[2*kbk][0],   sv[2*kbk][1]);
            pa[kbk][1] = pack_bf16(sv[2*kbk][2],   sv[2*kbk][3]);
            pa[kbk][2] = pack_bf16(sv[2*kbk+1][0], sv[2*kbk+1][1]);
            pa[kbk][3] = pack_bf16(sv[2*kbk+1][2], sv[2*kbk+1][3]);
        }

        // O += P V^T
        #pragma unroll
        for (int kbk = 0; kbk < 4; kbk++) {
            #pragma unroll
            for (int nb2 = 0; nb2 < 8; nb2++) {
                uint32_t b0, b1, b2, b3;
                LDSM_X4(b0, b1, b2, b3, vAddr + nb2*16*(KSTR*2) + kbk*32);
                MMA16816(O[2*nb2  ], pa[kbk][0], pa[kbk][1], pa[kbk][2], pa[kbk][3], b0, b1);
                MMA16816(O[2*nb2+1], pa[kbk][0], pa[kbk][1], pa[kbk][2], pa[kbk][3], b2, b3);
            }
        }
    }

    // Normalize + store att[b][(d*HH+h)][i] (bf16)
    float inv0 = 1.f / l0, inv1 = 1.f / l1;
    size_t obase = (size_t)b*CH*PP + (size_t)h*PP;
    int irow = i0 + 16*w + (lane >> 2);
    #pragma unroll
    for (int nb = 0; nb < 16; nb++) {
        int d0 = 8*nb + 2*(lane & 3);
        g_att[obase + (size_t)(d0  )*HH*PP + irow    ] = __float2bfloat16(O[nb][0] * inv0);
        g_att[obase + (size_t)(d0+1)*HH*PP + irow    ] = __float2bfloat16(O[nb][1] * inv0);
        g_att[obase + (size_t)(d0  )*HH*PP + irow + 8] = __float2bfloat16(O[nb][2] * inv1);
        g_att[obase + (size_t)(d0+1)*HH*PP + irow + 8] = __float2bfloat16(O[nb][3] * inv1);
    }
}

// ---------------------------------------------------------------------------
// Kernel 4: output projection on tensor cores + bias + residual (fp32 out).
// M=128, K=512 (4 chunks of 128), N=2048 per batch.
// ---------------------------------------------------------------------------
__global__ __launch_bounds__(256, 2) void out_mma_kernel(
        const float* __restrict__ Wo, const float* __restrict__ bo,
        const float* __restrict__ resid, float* __restrict__ out) {
    extern __shared__ char smraw[];
    __nv_bfloat16* Ws = (__nv_bfloat16*)smraw;   // [m=128][k=128]
    __nv_bfloat16* Xs = Ws + 128*WSTR;           // [k=128][p=128]

    int b  = blockIdx.z;
    int p0 = blockIdx.x * 128;
    int t  = threadIdx.x;
    int w = t >> 5, lane = t & 31;
    int wm = w & 3, wn = w >> 2;

    uint32_t aAddr = smem_u32(Ws)
        + (wm*32 + (lane&7) + 8*((lane>>3)&1)) * (WSTR*2)
        + ((lane>>4)&1) * 16;
    uint32_t bAddr = smem_u32(Xs)
        + ((lane&7) + 8*((lane>>3)&1)) * (XSTR*2)
        + ((lane>>4)&1) * 16
        + wn*128;

    float acc[2][8][4];
    #pragma unroll
    for (int i = 0; i < 2; i++)
        #pragma unroll
        for (int j = 0; j < 8; j++)
            acc[i][j][0] = acc[i][j][1] = acc[i][j][2] = acc[i][j][3] = 0.f;

    for (int chunk = 0; chunk < 4; chunk++) {
        __syncthreads();
        // Wo chunk [128][128] fp32 -> bf16
        #pragma unroll
        for (int it = 0; it < 16; it++) {
            int idx = t + it*256;
            int row = idx >> 5, col4 = idx & 31;
            float4 ww = *(const float4*)(Wo + (size_t)row*CH + chunk*128 + col4*4);
            uint2 pk; pk.x = pack_bf16(ww.x, ww.y); pk.y = pack_bf16(ww.z, ww.w);
            *(uint2*)(Ws + row*WSTR + col4*4) = pk;
        }
        // att chunk (already bf16) straight copy
        #pragma unroll
        for (int it = 0; it < 8; it++) {
            int idx = t + it*256;
            int c = idx >> 4, u = idx & 15;
            *(uint4*)(Xs + c*XSTR + u*8) =
                *(const uint4*)(g_att + (size_t)(b*CH + chunk*128 + c)*PP + p0 + u*8);
        }
        __syncthreads();

        #pragma unroll
        for (int kk = 0; kk < 8; kk++) {
            uint32_t a[2][4];
            LDSM_X4(a[0][0], a[0][1], a[0][2], a[0][3], aAddr + kk*32);
            LDSM_X4(a[1][0], a[1][1], a[1][2], a[1][3], aAddr + 16*(WSTR*2) + kk*32);
            #pragma unroll
            for (int nb2 = 0; nb2 < 4; nb2++) {
                uint32_t b0, b1, b2, b3;
                LDSM_X4_T(b0, b1, b2, b3, bAddr + kk*16*(XSTR*2) + nb2*32);
                #pragma unroll
                for (int mt2 = 0; mt2 < 2; mt2++) {
                    MMA16816(acc[mt2][2*nb2  ], a[mt2][0], a[mt2][1], a[mt2][2], a[mt2][3], b0, b1);
                    MMA16816(acc[mt2][2*nb2+1], a[mt2][0], a[mt2][1], a[mt2][2], a[mt2][3], b2, b3);
                }
            }
        }
    }

    // Epilogue: + bias + residual, fp32 store
    #pragma unroll
    for (int mt2 = 0; mt2 < 2; mt2++) {
        int r0 = wm*32 + mt2*16 + (lane >> 2);
        float bb0 = bo[r0], bb1 = bo[r0+8];
        #pragma unroll
        for (int nb = 0; nb < 8; nb++) {
            int n = p0 + wn*64 + nb*8 + (lane&3)*2;
            float2 rv0 = *(const float2*)(resid + (size_t)(b*CC + r0  )*PP + n);
            float2 rv1 = *(const float2*)(resid + (size_t)(b*CC + r0+8)*PP + n);
            float2 o0, o1;
            o0.x = acc[mt2][nb][0] + bb0 + rv0.x;
            o0.y = acc[mt2][nb][1] + bb0 + rv0.y;
            o1.x = acc[mt2][nb][2] + bb1 + rv1.x;
            o1.y = acc[mt2][nb][3] + bb1 + rv1.y;
            *(float2*)(out + (size_t)(b*CC + r0  )*PP + n) = o0;
            *(float2*)(out + (size_t)(b*CC + r0+8)*PP + n) = o1;
        }
    }
}

// ---------------------------------------------------------------------------
extern "C" void kernel_launch(void* const* d_in, const int* in_sizes, int n_in,
                              void* d_out, int out_size) {
    (void)in_sizes; (void)n_in; (void)out_size;
    const float* input = (const float*)d_in[0];
    const float* gamma = (const float*)d_in[1];
    const float* beta  = (const float*)d_in[2];
    const float* Wq = (const float*)d_in[3];
    const float* bq = (const float*)d_in[4];
    const float* Wk = (const float*)d_in[5];
    const float* bk = (const float*)d_in[6];
    const float* Wv = (const float*)d_in[7];
    const float* bv = (const float*)d_in[8];
    const float* Wo = (const float*)d_in[9];
    const float* bo = (const float*)d_in[10];
    float* out = (float*)d_out;

    cudaFuncSetAttribute(qkv_mma_kernel, cudaFuncAttributeMaxDynamicSharedMemorySize, QKV_SMEM);
    cudaFuncSetAttribute(flash_kernel, cudaFuncAttributeMaxDynamicSharedMemorySize, FLASH_SMEM);
    cudaFuncSetAttribute(out_mma_kernel, cudaFuncAttributeMaxDynamicSharedMemorySize, QKV_SMEM);

    bn_stats_kernel<<<128, 256>>>(input, gamma, beta);

    qkv_mma_kernel<<<dim3(16, 12, 8), 256, QKV_SMEM>>>(Wq, bq, Wk, bk, Wv, bv, input);

    flash_kernel<<<dim3(16, 4, 8), 256, FLASH_SMEM>>>();

    out_mma_kernel<<<dim3(16, 1, 8), 256, QKV_SMEM>>>(Wo, bo, input, out);
}